// round 9
// baseline (speedup 1.0000x reference)
#include <cuda_runtime.h>

// HashEmbedder: 16-level multires hash grid, F=2, IN_DIM=3, K=8 corners.
// Levels 0..5 dense (row-major), 6..15 hashed (XOR-prime, mod 524309).
// One thread per (point, level), interleaved R1 mapping (best measured).
// Hash gathers use the __ldcg intrinsic (L2-only, no L1 allocation) so the
// 42MB always-miss hash stream stops evicting the L1-resident dense tables.
// Unlike the R3 asm experiment, the intrinsic path lets ptxas front-batch the
// loads (MLP preserved) — isolating the caching effect from scheduling.

#define T_HASH 524309ULL
// Barrett magic: floor(2^64/T)+1. Exact for n < 2^38 (error term < 2^-45).
#define BARRETT_M ((0xFFFFFFFFFFFFFFFFULL / T_HASH) + 1ULL)

__device__ __forceinline__ unsigned int mod_T(unsigned long long n) {
    unsigned long long q = __umul64hi(n, BARRETT_M);
    return (unsigned int)(n - q * T_HASH);
}

// Per-level resolutions: int(16 * 1.38^i). All >0.04 from integer boundaries.
__device__ const int g_n[16] = {16,22,30,42,58,80,110,152,210,290,400,553,763,1053,1453,2005};
// ENTRIES_SIZE = float32(1.0/(n-1)) — same double->float rounding as numpy.
__device__ const float g_es[16] = {
    (float)(1.0/15.0),   (float)(1.0/21.0),   (float)(1.0/29.0),   (float)(1.0/41.0),
    (float)(1.0/57.0),   (float)(1.0/79.0),   (float)(1.0/109.0),  (float)(1.0/151.0),
    (float)(1.0/209.0),  (float)(1.0/289.0),  (float)(1.0/399.0),  (float)(1.0/552.0),
    (float)(1.0/762.0),  (float)(1.0/1052.0), (float)(1.0/1452.0), (float)(1.0/2004.0)};
// cumsum of n^3 for dense levels
__device__ const int g_base[6] = {0, 4096, 14744, 41744, 115832, 310944};

__global__ void __launch_bounds__(256)
hashenc_kernel(const float* __restrict__ xyz,
               const float* __restrict__ dense,
               const float* __restrict__ hasht,
               float* __restrict__ out,
               int npts)
{
    int idx = blockIdx.x * 256 + threadIdx.x;
    int p = idx >> 4;        // point
    if (p >= npts) return;
    int l = idx & 15;        // level

    float x0 = xyz[3 * p + 0];
    float x1 = xyz[3 * p + 1];
    float x2 = xyz[3 * p + 2];

    float* orow = out + (long long)p * 35;
    if (l == 0) {            // include_input passthrough (bounds [0,1] -> identity)
        orow[0] = x0; orow[1] = x1; orow[2] = x2;
    }

    float es  = g_es[l];
    int   n   = g_n[l];
    int   nm1 = n - 1;

    // flt = x / entries_size  (IEEE f32 divide, matching the reference exactly)
    float f0 = __fdiv_rn(x0, es);
    float f1 = __fdiv_rn(x1, es);
    float f2 = __fdiv_rn(x2, es);

    // trunc == floor (flt >= 0); flt+1 exact below 2^23.
    int i0 = (int)f0, i1 = (int)f1, i2 = (int)f2;
    int a0 = min(i0, nm1),     a1 = min(i1, nm1),     a2 = min(i2, nm1);
    int b0 = min(i0 + 1, nm1), b1 = min(i1 + 1, nm1), b2 = min(i2 + 1, nm1);

    // fractional offset from corner 0; weights use dims 0,1 only (as in source)
    float o0 = f0 - (float)a0;
    float o1 = f1 - (float)a1;
    float u0 = 1.0f - o0, u1 = 1.0f - o1;
    float w00 = u0 * u1, w01 = u0 * o1, w10 = o0 * u1, w11 = o0 * o1;

    float2 v0, v1, v2, v3, v4, v5, v6, v7;

    if (l < 6) {
        const float2* d2 = (const float2*)dense;
        int base = g_base[l];
        int s1 = n, s0 = n * n;
        int A0 = a0 * s0 + base, B0 = b0 * s0 + base;
        int A1 = a1 * s1,        B1 = b1 * s1;
        v0 = __ldg(d2 + (A0 + A1 + a2));
        v1 = __ldg(d2 + (A0 + A1 + b2));
        v2 = __ldg(d2 + (A0 + B1 + a2));
        v3 = __ldg(d2 + (A0 + B1 + b2));
        v4 = __ldg(d2 + (B0 + A1 + a2));
        v5 = __ldg(d2 + (B0 + A1 + b2));
        v6 = __ldg(d2 + (B0 + B1 + a2));
        v7 = __ldg(d2 + (B0 + B1 + b2));
    } else {
        const float2* h2 = (const float2*)hasht + (unsigned long long)(l - 6) * T_HASH;
        // ih = 1 ^ (x0*1) ^ (x1*19349663) ^ (x2*83492791), then % T
        unsigned long long A0h = 1ULL ^ (unsigned long long)(unsigned)a0;
        unsigned long long B0h = 1ULL ^ (unsigned long long)(unsigned)b0;
        unsigned long long A1h = (unsigned long long)(unsigned)a1 * 19349663ULL;
        unsigned long long B1h = (unsigned long long)(unsigned)b1 * 19349663ULL;
        unsigned long long A2h = (unsigned long long)(unsigned)a2 * 83492791ULL;
        unsigned long long B2h = (unsigned long long)(unsigned)b2 * 83492791ULL;
        v0 = __ldcg(h2 + mod_T(A0h ^ A1h ^ A2h));
        v1 = __ldcg(h2 + mod_T(A0h ^ A1h ^ B2h));
        v2 = __ldcg(h2 + mod_T(A0h ^ B1h ^ A2h));
        v3 = __ldcg(h2 + mod_T(A0h ^ B1h ^ B2h));
        v4 = __ldcg(h2 + mod_T(B0h ^ A1h ^ A2h));
        v5 = __ldcg(h2 + mod_T(B0h ^ A1h ^ B2h));
        v6 = __ldcg(h2 + mod_T(B0h ^ B1h ^ A2h));
        v7 = __ldcg(h2 + mod_T(B0h ^ B1h ^ B2h));
    }

    // corner i: dim0 bit = i>>2, dim1 bit = (i>>1)&1, dim2 bit = i&1 (weight ignores dim2)
    float rx = w00 * (v0.x + v1.x) + w01 * (v2.x + v3.x)
             + w10 * (v4.x + v5.x) + w11 * (v6.x + v7.x);
    float ry = w00 * (v0.y + v1.y) + w01 * (v2.y + v3.y)
             + w10 * (v4.y + v5.y) + w11 * (v6.y + v7.y);

    orow[3 + 2 * l] = rx;
    orow[4 + 2 * l] = ry;
}

extern "C" void kernel_launch(void* const* d_in, const int* in_sizes, int n_in,
                              void* d_out, int out_size) {
    const float* xyz   = (const float*)d_in[0];   // (2,65536,3) f32
    const float* dense = (const float*)d_in[1];   // (822944,2) f32
    const float* hasht = (const float*)d_in[2];   // (10,524309,2) f32
    float* out = (float*)d_out;                   // (2,65536,35) f32

    int npts = in_sizes[0] / 3;
    int total = npts * 16;
    int blocks = (total + 255) / 256;
    hashenc_kernel<<<blocks, 256>>>(xyz, dense, hasht, out, npts);
}

// round 11
// speedup vs baseline: 1.1047x; 1.1047x over previous
#include <cuda_runtime.h>

// HashEmbedder: 16-level multires hash grid, F=2, IN_DIM=3, K=8 corners.
// Levels 0..5 dense (row-major), 6..15 hashed (XOR-prime, mod 524309).
// ILP=2 variant of the best (R1) kernel: each thread processes ONE level for
// TWO points (p, p+npts/2). Same level => same dense/hash branch for both
// items (no extra divergence); 16 independent gathers are front-batched per
// thread (MLP 8 -> 16) to close any remaining latency exposure on the
// L1tex miss pipe. All table loads via __ldg (.ca — cache-op experiments
// regressed twice and are closed).

#define T_HASH 524309ULL
// Barrett magic: floor(2^64/T)+1. Exact for n < 2^38 (error term < 2^-45).
#define BARRETT_M ((0xFFFFFFFFFFFFFFFFULL / T_HASH) + 1ULL)

__device__ __forceinline__ unsigned int mod_T(unsigned long long n) {
    unsigned long long q = __umul64hi(n, BARRETT_M);
    return (unsigned int)(n - q * T_HASH);
}

// Per-level resolutions: int(16 * 1.38^i). All >0.04 from integer boundaries.
__device__ const int g_n[16] = {16,22,30,42,58,80,110,152,210,290,400,553,763,1053,1453,2005};
// ENTRIES_SIZE = float32(1.0/(n-1)) — same double->float rounding as numpy.
__device__ const float g_es[16] = {
    (float)(1.0/15.0),   (float)(1.0/21.0),   (float)(1.0/29.0),   (float)(1.0/41.0),
    (float)(1.0/57.0),   (float)(1.0/79.0),   (float)(1.0/109.0),  (float)(1.0/151.0),
    (float)(1.0/209.0),  (float)(1.0/289.0),  (float)(1.0/399.0),  (float)(1.0/552.0),
    (float)(1.0/762.0),  (float)(1.0/1052.0), (float)(1.0/1452.0), (float)(1.0/2004.0)};
// cumsum of n^3 for dense levels
__device__ const int g_base[6] = {0, 4096, 14744, 41744, 115832, 310944};

__global__ void __launch_bounds__(256)
hashenc_kernel(const float* __restrict__ xyz,
               const float* __restrict__ dense,
               const float* __restrict__ hasht,
               float* __restrict__ out,
               int npts)
{
    int idx = blockIdx.x * 256 + threadIdx.x;
    int half = npts >> 1;                  // npts = 131072, even
    int p0 = idx >> 4;                     // first point
    if (p0 >= half) return;
    int l = idx & 15;                      // level (same for both items)

    int   n   = g_n[l];
    int   nm1 = n - 1;
    float es  = g_es[l];

    int pp[2] = {p0, p0 + half};

    // Per-item state
    int   A0[2], B0[2], A1[2], B1[2], A2[2], B2[2];
    float w00[2], w01[2], w10[2], w11[2];
    float2 v[2][8];

    #pragma unroll
    for (int t = 0; t < 2; t++) {
        int p = pp[t];
        float x0 = xyz[3 * p + 0];
        float x1 = xyz[3 * p + 1];
        float x2 = xyz[3 * p + 2];

        if (l == 0) {    // include_input passthrough (bounds [0,1] -> identity)
            float* orow = out + (long long)p * 35;
            orow[0] = x0; orow[1] = x1; orow[2] = x2;
        }

        // flt = x / entries_size (IEEE f32 divide, matching reference exactly)
        float f0 = __fdiv_rn(x0, es);
        float f1 = __fdiv_rn(x1, es);
        float f2 = __fdiv_rn(x2, es);

        // trunc == floor (flt >= 0); flt+1 exact below 2^23.
        int i0 = (int)f0, i1 = (int)f1, i2 = (int)f2;
        int a0 = min(i0, nm1),     a1 = min(i1, nm1),     a2 = min(i2, nm1);
        int b0 = min(i0 + 1, nm1), b1 = min(i1 + 1, nm1), b2 = min(i2 + 1, nm1);

        float o0 = f0 - (float)a0;
        float o1 = f1 - (float)a1;
        float u0 = 1.0f - o0, u1 = 1.0f - o1;
        w00[t] = u0 * u1; w01[t] = u0 * o1; w10[t] = o0 * u1; w11[t] = o0 * o1;

        A0[t] = a0; B0[t] = b0; A1[t] = a1; B1[t] = b1; A2[t] = a2; B2[t] = b2;
    }

    if (l < 6) {
        const float2* d2 = (const float2*)dense;
        int base = g_base[l];
        int s1 = n, s0 = n * n;
        #pragma unroll
        for (int t = 0; t < 2; t++) {
            int a0s = A0[t] * s0 + base, b0s = B0[t] * s0 + base;
            int a1s = A1[t] * s1,        b1s = B1[t] * s1;
            v[t][0] = __ldg(d2 + (a0s + a1s + A2[t]));
            v[t][1] = __ldg(d2 + (a0s + a1s + B2[t]));
            v[t][2] = __ldg(d2 + (a0s + b1s + A2[t]));
            v[t][3] = __ldg(d2 + (a0s + b1s + B2[t]));
            v[t][4] = __ldg(d2 + (b0s + a1s + A2[t]));
            v[t][5] = __ldg(d2 + (b0s + a1s + B2[t]));
            v[t][6] = __ldg(d2 + (b0s + b1s + A2[t]));
            v[t][7] = __ldg(d2 + (b0s + b1s + B2[t]));
        }
    } else {
        const float2* h2 = (const float2*)hasht + (unsigned long long)(l - 6) * T_HASH;
        #pragma unroll
        for (int t = 0; t < 2; t++) {
            // ih = 1 ^ (x0*1) ^ (x1*19349663) ^ (x2*83492791), then % T
            unsigned long long A0h = 1ULL ^ (unsigned long long)(unsigned)A0[t];
            unsigned long long B0h = 1ULL ^ (unsigned long long)(unsigned)B0[t];
            unsigned long long A1h = (unsigned long long)(unsigned)A1[t] * 19349663ULL;
            unsigned long long B1h = (unsigned long long)(unsigned)B1[t] * 19349663ULL;
            unsigned long long A2h = (unsigned long long)(unsigned)A2[t] * 83492791ULL;
            unsigned long long B2h = (unsigned long long)(unsigned)B2[t] * 83492791ULL;
            v[t][0] = __ldg(h2 + mod_T(A0h ^ A1h ^ A2h));
            v[t][1] = __ldg(h2 + mod_T(A0h ^ A1h ^ B2h));
            v[t][2] = __ldg(h2 + mod_T(A0h ^ B1h ^ A2h));
            v[t][3] = __ldg(h2 + mod_T(A0h ^ B1h ^ B2h));
            v[t][4] = __ldg(h2 + mod_T(B0h ^ A1h ^ A2h));
            v[t][5] = __ldg(h2 + mod_T(B0h ^ A1h ^ B2h));
            v[t][6] = __ldg(h2 + mod_T(B0h ^ B1h ^ A2h));
            v[t][7] = __ldg(h2 + mod_T(B0h ^ B1h ^ B2h));
        }
    }

    #pragma unroll
    for (int t = 0; t < 2; t++) {
        float rx = w00[t] * (v[t][0].x + v[t][1].x) + w01[t] * (v[t][2].x + v[t][3].x)
                 + w10[t] * (v[t][4].x + v[t][5].x) + w11[t] * (v[t][6].x + v[t][7].x);
        float ry = w00[t] * (v[t][0].y + v[t][1].y) + w01[t] * (v[t][2].y + v[t][3].y)
                 + w10[t] * (v[t][4].y + v[t][5].y) + w11[t] * (v[t][6].y + v[t][7].y);
        float* orow = out + (long long)pp[t] * 35;
        orow[3 + 2 * l] = rx;   // row stride 35 floats (odd) -> 8B alignment not
        orow[4 + 2 * l] = ry;   // guaranteed; keep two scalar stores
    }
}

extern "C" void kernel_launch(void* const* d_in, const int* in_sizes, int n_in,
                              void* d_out, int out_size) {
    const float* xyz   = (const float*)d_in[0];   // (2,65536,3) f32
    const float* dense = (const float*)d_in[1];   // (822944,2) f32
    const float* hasht = (const float*)d_in[2];   // (10,524309,2) f32
    float* out = (float*)d_out;                   // (2,65536,35) f32

    int npts = in_sizes[0] / 3;
    int total = (npts / 2) * 16;                  // npts even (131072)
    int blocks = (total + 255) / 256;
    hashenc_kernel<<<blocks, 256>>>(xyz, dense, hasht, out, npts);
}